// round 6
// baseline (speedup 1.0000x reference)
#include <cuda_runtime.h>
#include <cuda_bf16.h>
#include <cstdint>

// Problem constants (from reference)
#define NN 50000   // nodes
#define MM 10000   // hyperedges (static segment count)
#define EE 500000  // incidence pairs (max)
#define DD 128     // feature dim

// ---------------- static scratch (no allocations allowed) ----------------
__device__ float g_emean[MM * DD];   // seg_mean of raw x over edges   5.1 MB
__device__ float g_eproj[MM * DD];   // emean @ Wveu                   5.1 MB
__device__ float g_nmean[NN * DD];   // node means (output space)     25.6 MB
__device__ float g_wvu  [DD * DD];   // W_v @ W_u_top
__device__ float g_wveu [DD * DD];   // W_v @ W_e @ W_u_bot
__device__ int   g_ecnt [MM];
__device__ int   g_ncnt [NN];
__device__ int   g_eofs [MM + 1];
__device__ int   g_nofs [NN + 1];
__device__ int   g_ecur [MM];
__device__ int   g_ncur [NN];
__device__ int   g_ecsr [EE];        // row index per edge, grouped by hyperedge
__device__ int   g_ncsr [EE];        // hyperedge index per edge, grouped by node
__device__ int   g_colmin;

// ---------------- init counters ----------------
__global__ void k_init_cnt() {
    int i = blockIdx.x * blockDim.x + threadIdx.x;
    int stride = gridDim.x * blockDim.x;
    for (int j = i; j < NN; j += stride) g_ncnt[j] = 0;
    for (int j = i; j < MM; j += stride) g_ecnt[j] = 0;
    if (i == 0) g_colmin = 0x7fffffff;
}

// ---------------- col min reduction ----------------
__global__ void k_colmin(const int* __restrict__ col, int E) {
    int v = 0x7fffffff;
    for (int j = blockIdx.x * blockDim.x + threadIdx.x; j < E;
         j += gridDim.x * blockDim.x)
        v = min(v, col[j]);
#pragma unroll
    for (int o = 16; o > 0; o >>= 1) v = min(v, __shfl_down_sync(0xffffffffu, v, o));
    if ((threadIdx.x & 31) == 0) atomicMin(&g_colmin, v);
}

// ---------------- degree histograms ----------------
__global__ void k_hist(const int* __restrict__ row, const int* __restrict__ col, int E) {
    const int cmin = g_colmin;
    for (int e = blockIdx.x * blockDim.x + threadIdx.x; e < E;
         e += gridDim.x * blockDim.x) {
        atomicAdd(&g_ecnt[__ldg(&col[e]) - cmin], 1);
        atomicAdd(&g_ncnt[__ldg(&row[e])], 1);
    }
}

// ---------------- single-block exclusive scan (chunked Hillis-Steele) ----------------
__global__ void __launch_bounds__(1024) k_scan(
    const int* __restrict__ cnt, int* __restrict__ ofs, int* __restrict__ cur, int n)
{
    __shared__ int sh[1024];
    const int t = threadIdx.x;
    const int chunk = (n + 1023) >> 10;
    const int b = t * chunk;
    const int e = min(b + chunk, n);
    int s = 0;
    for (int i = b; i < e; i++) s += cnt[i];
    sh[t] = s;
    __syncthreads();
#pragma unroll
    for (int d = 1; d < 1024; d <<= 1) {
        int v = (t >= d) ? sh[t - d] : 0;
        __syncthreads();
        sh[t] += v;
        __syncthreads();
    }
    int run = (t > 0) ? sh[t - 1] : 0;
    for (int i = b; i < e; i++) {
        ofs[i] = run;
        cur[i] = run;
        run += cnt[i];
    }
    if (t == 0) ofs[n] = sh[1023];
}

// ---------------- CSR placement (both directions) ----------------
__global__ void k_place(const int* __restrict__ row, const int* __restrict__ col, int E) {
    const int cmin = g_colmin;
    for (int e = blockIdx.x * blockDim.x + threadIdx.x; e < E;
         e += gridDim.x * blockDim.x) {
        int r = __ldg(&row[e]);
        int c = __ldg(&col[e]) - cmin;
        int pe = atomicAdd(&g_ecur[c], 1);
        g_ecsr[pe] = r;
        int pn = atomicAdd(&g_ncur[r], 1);
        g_ncsr[pn] = c;
    }
}

// ---------------- weight combos: Wvu = Wv@Wu_top ; Wveu = Wv@We@Wu_bot ----------------
__global__ void __launch_bounds__(128) k_combo(
    const float* __restrict__ Wv, const float* __restrict__ We,
    const float* __restrict__ Wu)
{
    __shared__ float rowv[DD];
    __shared__ float tmp[DD];
    const int c = threadIdx.x;
    const int b = blockIdx.x;
    const float* Wu_top = Wu;
    const float* Wu_bot = Wu + DD * DD;

    if (b < DD) {
        const int r = b;
        rowv[c] = Wv[r * DD + c];
        __syncthreads();
        float a0 = 0.f, a1 = 0.f;
#pragma unroll
        for (int k = 0; k < DD; k += 2) {
            a0 = fmaf(rowv[k],     Wu_top[(k)     * DD + c], a0);
            a1 = fmaf(rowv[k + 1], Wu_top[(k + 1) * DD + c], a1);
        }
        g_wvu[r * DD + c] = a0 + a1;
    } else {
        const int r = b - DD;
        rowv[c] = Wv[r * DD + c];
        __syncthreads();
        float a0 = 0.f, a1 = 0.f;
#pragma unroll
        for (int k = 0; k < DD; k += 2) {
            a0 = fmaf(rowv[k],     We[(k)     * DD + c], a0);
            a1 = fmaf(rowv[k + 1], We[(k + 1) * DD + c], a1);
        }
        tmp[c] = a0 + a1;
        __syncthreads();
        float b0 = 0.f, b1 = 0.f;
#pragma unroll
        for (int k = 0; k < DD; k += 2) {
            b0 = fmaf(tmp[k],     Wu_bot[(k)     * DD + c], b0);
            b1 = fmaf(tmp[k + 1], Wu_bot[(k + 1) * DD + c], b1);
        }
        g_wveu[r * DD + c] = b0 + b1;
    }
}

// ---------------- gather 1: per-hyperedge mean of raw x ----------------
__global__ void k_gather_e(const float* __restrict__ x) {
    const int lane = threadIdx.x & 31;
    const int seg = (blockIdx.x * blockDim.x + threadIdx.x) >> 5;
    if (seg >= MM) return;
    const int beg = g_eofs[seg];
    const int end = g_eofs[seg + 1];
    float4 acc = make_float4(0.f, 0.f, 0.f, 0.f);
    int i = beg;
    for (; i + 1 < end; i += 2) {
        int r0 = g_ecsr[i];
        int r1 = g_ecsr[i + 1];
        float4 v0 = *(const float4*)&x[(size_t)r0 * DD + lane * 4];
        float4 v1 = *(const float4*)&x[(size_t)r1 * DD + lane * 4];
        acc.x += v0.x + v1.x; acc.y += v0.y + v1.y;
        acc.z += v0.z + v1.z; acc.w += v0.w + v1.w;
    }
    if (i < end) {
        int r0 = g_ecsr[i];
        float4 v0 = *(const float4*)&x[(size_t)r0 * DD + lane * 4];
        acc.x += v0.x; acc.y += v0.y; acc.z += v0.z; acc.w += v0.w;
    }
    float inv = 1.0f / fmaxf((float)(end - beg), 1.0f);
    acc.x *= inv; acc.y *= inv; acc.z *= inv; acc.w *= inv;
    *(float4*)&g_emean[(size_t)seg * DD + lane * 4] = acc;
}

// ---------------- gather 2: per-node mean of eproj ----------------
__global__ void k_gather_n() {
    const int lane = threadIdx.x & 31;
    const int seg = (blockIdx.x * blockDim.x + threadIdx.x) >> 5;
    if (seg >= NN) return;
    const int beg = g_nofs[seg];
    const int end = g_nofs[seg + 1];
    float4 acc = make_float4(0.f, 0.f, 0.f, 0.f);
    int i = beg;
    for (; i + 1 < end; i += 2) {
        int c0 = g_ncsr[i];
        int c1 = g_ncsr[i + 1];
        float4 v0 = *(const float4*)&g_eproj[(size_t)c0 * DD + lane * 4];
        float4 v1 = *(const float4*)&g_eproj[(size_t)c1 * DD + lane * 4];
        acc.x += v0.x + v1.x; acc.y += v0.y + v1.y;
        acc.z += v0.z + v1.z; acc.w += v0.w + v1.w;
    }
    if (i < end) {
        int c0 = g_ncsr[i];
        float4 v0 = *(const float4*)&g_eproj[(size_t)c0 * DD + lane * 4];
        acc.x += v0.x; acc.y += v0.y; acc.z += v0.z; acc.w += v0.w;
    }
    float inv = 1.0f / fmaxf((float)(end - beg), 1.0f);
    acc.x *= inv; acc.y *= inv; acc.z *= inv; acc.w *= inv;
    *(float4*)&g_nmean[(size_t)seg * DD + lane * 4] = acc;
}

// ---------------- double-buffered SGEMM body: C = A[Mrows x 128] @ B[128 x 128] ----------------
// FINAL: C = relu(acc + nmean[row] + bias)
template <bool FINAL>
__device__ __forceinline__ void gemm_body(
    const float* __restrict__ A0, const float* __restrict__ Bm,
    const float* __restrict__ bias, float* __restrict__ C, int Mrows)
{
    __shared__ float As[2][16][132];
    __shared__ float Bs[2][16][128];

    const int tid = threadIdx.x;
    const int ty = tid >> 4;   // 0..15
    const int tx = tid & 15;   // 0..15
    const int rowBase = blockIdx.x * 128;

    const int aRow = tid >> 2;        // 0..63
    const int aCol = (tid & 3) << 2;  // 0,4,8,12
    const int bRow = tid >> 5;        // 0..7
    const int bCol = (tid & 31) << 2; // 0..124

    float acc[8][8];
#pragma unroll
    for (int i = 0; i < 8; i++)
#pragma unroll
        for (int j = 0; j < 8; j++) acc[i][j] = 0.0f;

    float4 pa[2], pb[2];
#pragma unroll
    for (int p = 0; p < 2; p++) {
        int gr = rowBase + aRow + p * 64;
        pa[p] = make_float4(0.f, 0.f, 0.f, 0.f);
        if (gr < Mrows) pa[p] = *(const float4*)&A0[(size_t)gr * DD + aCol];
        pb[p] = *(const float4*)&Bm[(size_t)(bRow + p * 8) * DD + bCol];
    }
#pragma unroll
    for (int p = 0; p < 2; p++) {
        int r = aRow + p * 64;
        As[0][aCol + 0][r] = pa[p].x;
        As[0][aCol + 1][r] = pa[p].y;
        As[0][aCol + 2][r] = pa[p].z;
        As[0][aCol + 3][r] = pa[p].w;
        *(float4*)&Bs[0][bRow + p * 8][bCol] = pb[p];
    }
    __syncthreads();

#pragma unroll
    for (int kb = 0; kb < 8; kb++) {
        if (kb < 7) {
            const int ko = (kb + 1) * 16;
#pragma unroll
            for (int p = 0; p < 2; p++) {
                int gr = rowBase + aRow + p * 64;
                pa[p] = make_float4(0.f, 0.f, 0.f, 0.f);
                if (gr < Mrows) pa[p] = *(const float4*)&A0[(size_t)gr * DD + ko + aCol];
                pb[p] = *(const float4*)&Bm[(size_t)(ko + bRow + p * 8) * DD + bCol];
            }
        }
        const int cb = kb & 1;
#pragma unroll
        for (int k = 0; k < 16; k++) {
            float ar[8], br[8];
            *(float4*)&ar[0] = *(const float4*)&As[cb][k][ty * 8];
            *(float4*)&ar[4] = *(const float4*)&As[cb][k][ty * 8 + 4];
            *(float4*)&br[0] = *(const float4*)&Bs[cb][k][tx * 8];
            *(float4*)&br[4] = *(const float4*)&Bs[cb][k][tx * 8 + 4];
#pragma unroll
            for (int i = 0; i < 8; i++)
#pragma unroll
                for (int j = 0; j < 8; j++)
                    acc[i][j] = fmaf(ar[i], br[j], acc[i][j]);
        }
        if (kb < 7) {
            const int nb = cb ^ 1;
#pragma unroll
            for (int p = 0; p < 2; p++) {
                int r = aRow + p * 64;
                As[nb][aCol + 0][r] = pa[p].x;
                As[nb][aCol + 1][r] = pa[p].y;
                As[nb][aCol + 2][r] = pa[p].z;
                As[nb][aCol + 3][r] = pa[p].w;
                *(float4*)&Bs[nb][bRow + p * 8][bCol] = pb[p];
            }
            __syncthreads();
        }
    }

#pragma unroll
    for (int i = 0; i < 8; i++) {
        int gr = rowBase + ty * 8 + i;
        if (gr >= Mrows) continue;
#pragma unroll
        for (int j = 0; j < 8; j += 4) {
            int gc = tx * 8 + j;
            float4 v = make_float4(acc[i][j], acc[i][j + 1], acc[i][j + 2], acc[i][j + 3]);
            if (FINAL) {
                float4 s = *(const float4*)&g_nmean[(size_t)gr * DD + gc];
                v.x = fmaxf(v.x + s.x + __ldg(&bias[gc + 0]), 0.0f);
                v.y = fmaxf(v.y + s.y + __ldg(&bias[gc + 1]), 0.0f);
                v.z = fmaxf(v.z + s.z + __ldg(&bias[gc + 2]), 0.0f);
                v.w = fmaxf(v.w + s.w + __ldg(&bias[gc + 3]), 0.0f);
            }
            *(float4*)&C[(size_t)gr * DD + gc] = v;
        }
    }
}

__global__ void __launch_bounds__(256, 2) k_gemm_plain(
    const float* A, const float* B, float* C, int Mrows)
{
    gemm_body<false>(A, B, nullptr, C, Mrows);
}

__global__ void __launch_bounds__(256, 2) k_gemm_final(
    const float* A, const float* B, const float* bias, float* C, int Mrows)
{
    gemm_body<true>(A, B, bias, C, Mrows);
}

// ---------------- launch ----------------
extern "C" void kernel_launch(void* const* d_in, const int* in_sizes, int n_in,
                              void* d_out, int out_size)
{
    const float* x   = (const float*)d_in[0];   // (N, 128)
    const int*   ei  = (const int*)  d_in[1];   // (2, E): row then col
    const float* Wv  = (const float*)d_in[2];   // (128, 128)
    const float* We  = (const float*)d_in[3];   // (128, 128)
    const float* Wu  = (const float*)d_in[4];   // (256, 128)
    const float* bu  = (const float*)d_in[5];   // (128,)
    float* out = (float*)d_out;                 // (N, 128)

    const int E = in_sizes[1] / 2;
    const int N = in_sizes[0] / DD;
    const int* rowp = ei;
    const int* colp = ei + E;

    float* emean; cudaGetSymbolAddress((void**)&emean, g_emean);
    float* eproj; cudaGetSymbolAddress((void**)&eproj, g_eproj);
    float* wvu;   cudaGetSymbolAddress((void**)&wvu,   g_wvu);
    float* wveu;  cudaGetSymbolAddress((void**)&wveu,  g_wveu);
    int* ecnt;    cudaGetSymbolAddress((void**)&ecnt,  g_ecnt);
    int* ncnt;    cudaGetSymbolAddress((void**)&ncnt,  g_ncnt);
    int* eofs;    cudaGetSymbolAddress((void**)&eofs,  g_eofs);
    int* nofs;    cudaGetSymbolAddress((void**)&nofs,  g_nofs);
    int* ecur;    cudaGetSymbolAddress((void**)&ecur,  g_ecur);
    int* ncur;    cudaGetSymbolAddress((void**)&ncur,  g_ncur);

    // 1. counters + colmin
    k_init_cnt<<<64, 256>>>();
    k_colmin<<<512, 256>>>(colp, E);
    // 2. degree histograms, prefix scans, CSR placement
    k_hist<<<1024, 256>>>(rowp, colp, E);
    k_scan<<<1, 1024>>>(ecnt, eofs, ecur, MM);
    k_scan<<<1, 1024>>>(ncnt, nofs, ncur, NN);
    k_place<<<1024, 256>>>(rowp, colp, E);
    // 3. weight combos
    k_combo<<<256, 128>>>(Wv, We, Wu);
    // 4. per-hyperedge mean of raw x
    k_gather_e<<<(MM * 32 + 255) / 256, 256>>>(x);
    // 5. eproj = emean @ Wveu  (output space)
    k_gemm_plain<<<(MM + 127) / 128, 256>>>(emean, wveu, eproj, MM);
    // 6. per-node mean of eproj
    k_gather_n<<<(NN * 32 + 255) / 256, 256>>>();
    // 7. out = relu(x@Wvu + nmean + bias)
    k_gemm_final<<<(N + 127) / 128, 256>>>(x, wvu, bu, out, N);
}

// round 8
// speedup vs baseline: 1.2697x; 1.2697x over previous
#include <cuda_runtime.h>
#include <cuda_bf16.h>
#include <cstdint>

#define NN 50000   // nodes
#define MM 10000   // hyperedges
#define DD 128     // feature dim

// ---------------- static scratch ----------------
__device__ float g_esum [MM * DD];   // hyperedge sums                 5.1 MB
__device__ float g_eproj[MM * DD];   // (esum/cnt) @ Wveu              5.1 MB
__device__ float g_nsum [NN * DD];   // node sums (output space)      25.6 MB
__device__ float g_xout [NN * DD];   // x @ Wvu                       25.6 MB
__device__ float g_wvu  [DD * DD];   // W_v @ W_u_top
__device__ float g_wveu [DD * DD];   // W_v @ W_e @ W_u_bot
__device__ int   g_ecnt [MM];
__device__ int   g_ncnt [NN];
__device__ int   g_colmin = 0x7fffffff;   // idempotent across runs (atomicMin of same data)

// ---------------- init: zero accumulators + colmin (fused) ----------------
__global__ void k_init(const int* __restrict__ col, int E) {
    int i = blockIdx.x * blockDim.x + threadIdx.x;
    int stride = gridDim.x * blockDim.x;
    float4 z = make_float4(0.f, 0.f, 0.f, 0.f);
    for (int j = i; j < NN * DD / 4; j += stride) ((float4*)g_nsum)[j] = z;
    for (int j = i; j < MM * DD / 4; j += stride) ((float4*)g_esum)[j] = z;
    for (int j = i; j < NN; j += stride) g_ncnt[j] = 0;
    for (int j = i; j < MM; j += stride) g_ecnt[j] = 0;
    // col min (g_colmin statically initialized; atomicMin is idempotent across replays)
    int v = 0x7fffffff;
    for (int j = i; j < E; j += stride) v = min(v, __ldg(&col[j]));
#pragma unroll
    for (int o = 16; o > 0; o >>= 1) v = min(v, __shfl_down_sync(0xffffffffu, v, o));
    if ((threadIdx.x & 31) == 0) atomicMin(&g_colmin, v);
}

// ---------------- weight combos: Wvu = Wv@Wu_top ; Wveu = Wv@We@Wu_bot ----------------
__global__ void __launch_bounds__(128) k_combo(
    const float* __restrict__ Wv, const float* __restrict__ We,
    const float* __restrict__ Wu)
{
    __shared__ float rowv[DD];
    __shared__ float tmp[DD];
    const int c = threadIdx.x;
    const int b = blockIdx.x;
    const float* Wu_top = Wu;
    const float* Wu_bot = Wu + DD * DD;

    if (b < DD) {
        const int r = b;
        rowv[c] = Wv[r * DD + c];
        __syncthreads();
        float a0 = 0.f, a1 = 0.f;
#pragma unroll
        for (int k = 0; k < DD; k += 2) {
            a0 = fmaf(rowv[k],     Wu_top[(k)     * DD + c], a0);
            a1 = fmaf(rowv[k + 1], Wu_top[(k + 1) * DD + c], a1);
        }
        g_wvu[r * DD + c] = a0 + a1;
    } else {
        const int r = b - DD;
        rowv[c] = Wv[r * DD + c];
        __syncthreads();
        float a0 = 0.f, a1 = 0.f;
#pragma unroll
        for (int k = 0; k < DD; k += 2) {
            a0 = fmaf(rowv[k],     We[(k)     * DD + c], a0);
            a1 = fmaf(rowv[k + 1], We[(k + 1) * DD + c], a1);
        }
        tmp[c] = a0 + a1;
        __syncthreads();
        float b0 = 0.f, b1 = 0.f;
#pragma unroll
        for (int k = 0; k < DD; k += 2) {
            b0 = fmaf(tmp[k],     Wu_bot[(k)     * DD + c], b0);
            b1 = fmaf(tmp[k + 1], Wu_bot[(k + 1) * DD + c], b1);
        }
        g_wveu[r * DD + c] = b0 + b1;
    }
}

// ---------------- vector float atomic add (sm_90+) ----------------
__device__ __forceinline__ void red_add_v4(float* p, float4 v) {
    asm volatile("red.global.add.v4.f32 [%0], {%1,%2,%3,%4};"
                 :: "l"(p), "f"(v.x), "f"(v.y), "f"(v.z), "f"(v.w) : "memory");
}

// ---------------- scatter 1: raw node features -> hyperedge sums ----------------
__global__ void k_scatter1(const float* __restrict__ x,
                           const int* __restrict__ row, const int* __restrict__ col, int E) {
    const int cmin = g_colmin;
    const int lane = threadIdx.x & 31;
    const int warp = (blockIdx.x * blockDim.x + threadIdx.x) >> 5;
    const int nw   = (gridDim.x * blockDim.x) >> 5;
    for (int e = warp; e < E; e += nw) {
        int r = __ldg(&row[e]);
        int c = __ldg(&col[e]) - cmin;
        float4 v = *(const float4*)&x[(size_t)r * DD + lane * 4];
        red_add_v4(&g_esum[(size_t)c * DD + lane * 4], v);
        if (lane == 0) atomicAdd(&g_ecnt[c], 1);
    }
}

// ---------------- scatter 2: hyperedge features (output space) -> node sums ----------------
__global__ void k_scatter2(const int* __restrict__ row, const int* __restrict__ col, int E) {
    const int cmin = g_colmin;
    const int lane = threadIdx.x & 31;
    const int warp = (blockIdx.x * blockDim.x + threadIdx.x) >> 5;
    const int nw   = (gridDim.x * blockDim.x) >> 5;
    for (int e = warp; e < E; e += nw) {
        int r = __ldg(&row[e]);
        int c = __ldg(&col[e]) - cmin;
        float4 v = *(const float4*)&g_eproj[(size_t)c * DD + lane * 4];
        red_add_v4(&g_nsum[(size_t)r * DD + lane * 4], v);
        if (lane == 0) atomicAdd(&g_ncnt[r], 1);
    }
}

// ---------------- double-buffered SGEMM body: C = A[Mrows x 128] @ B[128 x 128] ----------------
// SCALE: A rows scaled by 1/max(cnt[row],1) (segment-mean fold, hoisted)
template <bool SCALE>
__device__ __forceinline__ void gemm_body(
    const float* __restrict__ A0, const int* __restrict__ cnt0,
    const float* __restrict__ Bm, float* __restrict__ C, int Mrows)
{
    __shared__ float As[2][16][132];
    __shared__ float Bs[2][16][128];

    const int tid = threadIdx.x;
    const int ty = tid >> 4;
    const int tx = tid & 15;
    const int rowBase = blockIdx.x * 128;

    const int aRow = tid >> 2;
    const int aCol = (tid & 3) << 2;
    const int bRow = tid >> 5;
    const int bCol = (tid & 31) << 2;

    float scl[2] = {1.0f, 1.0f};
    if (SCALE) {
#pragma unroll
        for (int p = 0; p < 2; p++) {
            int gr = rowBase + aRow + p * 64;
            if (gr < Mrows) scl[p] = 1.0f / fmaxf((float)__ldg(&cnt0[gr]), 1.0f);
        }
    }

    float acc[8][8];
#pragma unroll
    for (int i = 0; i < 8; i++)
#pragma unroll
        for (int j = 0; j < 8; j++) acc[i][j] = 0.0f;

    float4 pa[2], pb[2];
#pragma unroll
    for (int p = 0; p < 2; p++) {
        int gr = rowBase + aRow + p * 64;
        pa[p] = make_float4(0.f, 0.f, 0.f, 0.f);
        if (gr < Mrows) {
            pa[p] = *(const float4*)&A0[(size_t)gr * DD + aCol];
            if (SCALE) { pa[p].x *= scl[p]; pa[p].y *= scl[p]; pa[p].z *= scl[p]; pa[p].w *= scl[p]; }
        }
        pb[p] = *(const float4*)&Bm[(size_t)(bRow + p * 8) * DD + bCol];
    }
#pragma unroll
    for (int p = 0; p < 2; p++) {
        int r = aRow + p * 64;
        As[0][aCol + 0][r] = pa[p].x;
        As[0][aCol + 1][r] = pa[p].y;
        As[0][aCol + 2][r] = pa[p].z;
        As[0][aCol + 3][r] = pa[p].w;
        *(float4*)&Bs[0][bRow + p * 8][bCol] = pb[p];
    }
    __syncthreads();

#pragma unroll
    for (int kb = 0; kb < 8; kb++) {
        if (kb < 7) {
            const int ko = (kb + 1) * 16;
#pragma unroll
            for (int p = 0; p < 2; p++) {
                int gr = rowBase + aRow + p * 64;
                pa[p] = make_float4(0.f, 0.f, 0.f, 0.f);
                if (gr < Mrows) {
                    pa[p] = *(const float4*)&A0[(size_t)gr * DD + ko + aCol];
                    if (SCALE) { pa[p].x *= scl[p]; pa[p].y *= scl[p]; pa[p].z *= scl[p]; pa[p].w *= scl[p]; }
                }
                pb[p] = *(const float4*)&Bm[(size_t)(ko + bRow + p * 8) * DD + bCol];
            }
        }
        const int cb = kb & 1;
#pragma unroll
        for (int k = 0; k < 16; k++) {
            float ar[8], br[8];
            *(float4*)&ar[0] = *(const float4*)&As[cb][k][ty * 8];
            *(float4*)&ar[4] = *(const float4*)&As[cb][k][ty * 8 + 4];
            *(float4*)&br[0] = *(const float4*)&Bs[cb][k][tx * 8];
            *(float4*)&br[4] = *(const float4*)&Bs[cb][k][tx * 8 + 4];
#pragma unroll
            for (int i = 0; i < 8; i++)
#pragma unroll
                for (int j = 0; j < 8; j++)
                    acc[i][j] = fmaf(ar[i], br[j], acc[i][j]);
        }
        if (kb < 7) {
            const int nb = cb ^ 1;
#pragma unroll
            for (int p = 0; p < 2; p++) {
                int r = aRow + p * 64;
                As[nb][aCol + 0][r] = pa[p].x;
                As[nb][aCol + 1][r] = pa[p].y;
                As[nb][aCol + 2][r] = pa[p].z;
                As[nb][aCol + 3][r] = pa[p].w;
                *(float4*)&Bs[nb][bRow + p * 8][bCol] = pb[p];
            }
            __syncthreads();
        }
    }

#pragma unroll
    for (int i = 0; i < 8; i++) {
        int gr = rowBase + ty * 8 + i;
        if (gr >= Mrows) continue;
#pragma unroll
        for (int j = 0; j < 8; j += 4) {
            int gc = tx * 8 + j;
            float4 v = make_float4(acc[i][j], acc[i][j + 1], acc[i][j + 2], acc[i][j + 3]);
            *(float4*)&C[(size_t)gr * DD + gc] = v;
        }
    }
}

__global__ void __launch_bounds__(256, 2) k_gemm_plain(
    const float* A, const float* B, float* C, int Mrows)
{
    gemm_body<false>(A, nullptr, B, C, Mrows);
}

__global__ void __launch_bounds__(256, 2) k_gemm_scale(
    const float* A, const int* cnt, const float* B, float* C, int Mrows)
{
    gemm_body<true>(A, cnt, B, C, Mrows);
}

// ---------------- final fused epilogue: out = relu(xout + nsum/cnt + b) ----------------
__global__ void k_final(const float* __restrict__ bias, float* __restrict__ out, int N) {
    int total = N * (DD / 4);
    for (int i = blockIdx.x * blockDim.x + threadIdx.x; i < total;
         i += gridDim.x * blockDim.x) {
        int r  = i >> 5;
        int cg = i & 31;
        float4 a = *(const float4*)&g_xout[(size_t)i * 4];
        float4 s = *(const float4*)&g_nsum[(size_t)i * 4];
        float inv = 1.0f / fmaxf((float)__ldg(&g_ncnt[r]), 1.0f);
        float4 b = *(const float4*)&bias[cg * 4];
        float4 o;
        o.x = fmaxf(fmaf(s.x, inv, a.x) + b.x, 0.0f);
        o.y = fmaxf(fmaf(s.y, inv, a.y) + b.y, 0.0f);
        o.z = fmaxf(fmaf(s.z, inv, a.z) + b.z, 0.0f);
        o.w = fmaxf(fmaf(s.w, inv, a.w) + b.w, 0.0f);
        *(float4*)&out[(size_t)i * 4] = o;
    }
}

// ---------------- launch ----------------
extern "C" void kernel_launch(void* const* d_in, const int* in_sizes, int n_in,
                              void* d_out, int out_size)
{
    const float* x   = (const float*)d_in[0];   // (N, 128)
    const int*   ei  = (const int*)  d_in[1];   // (2, E): row then col
    const float* Wv  = (const float*)d_in[2];   // (128, 128)
    const float* We  = (const float*)d_in[3];   // (128, 128)
    const float* Wu  = (const float*)d_in[4];   // (256, 128)
    const float* bu  = (const float*)d_in[5];   // (128,)
    float* out = (float*)d_out;                 // (N, 128)

    const int E = in_sizes[1] / 2;
    const int N = in_sizes[0] / DD;
    const int* rowp = ei;
    const int* colp = ei + E;

    float* esum;  cudaGetSymbolAddress((void**)&esum,  g_esum);
    float* eproj; cudaGetSymbolAddress((void**)&eproj, g_eproj);
    float* xout;  cudaGetSymbolAddress((void**)&xout,  g_xout);
    float* wvu;   cudaGetSymbolAddress((void**)&wvu,   g_wvu);
    float* wveu;  cudaGetSymbolAddress((void**)&wveu,  g_wveu);
    int* ecnt;    cudaGetSymbolAddress((void**)&ecnt,  g_ecnt);

    // side stream + fork/join events (created & destroyed per call; no device mem)
    cudaStream_t side;
    cudaStreamCreateWithFlags(&side, cudaStreamNonBlocking);
    cudaEvent_t evFork, evJoin;
    cudaEventCreateWithFlags(&evFork, cudaEventDisableTiming);
    cudaEventCreateWithFlags(&evJoin, cudaEventDisableTiming);

    // main stream: init (zero + colmin), weight combos
    k_init<<<512, 256>>>(colp, E);
    k_combo<<<256, 128>>>(Wv, We, Wu);

    // fork: xout = x @ Wvu on side stream (FFMA-bound), overlapped with
    // the LTS-bound scatter chain on the main stream
    cudaEventRecord(evFork, 0);
    cudaStreamWaitEvent(side, evFork, 0);
    k_gemm_plain<<<(N + 127) / 128, 256, 0, side>>>(x, wvu, xout, N);
    cudaEventRecord(evJoin, side);

    // main stream: scatter1 -> gemm_scale -> scatter2
    k_scatter1<<<4096, 256>>>(x, rowp, colp, E);
    k_gemm_scale<<<(MM + 127) / 128, 256>>>(esum, ecnt, wveu, eproj, MM);
    k_scatter2<<<4096, 256>>>(rowp, colp, E);

    // join, then fused epilogue
    cudaStreamWaitEvent(0, evJoin, 0);
    k_final<<<2048, 256>>>(bu, out, N);

    cudaEventDestroy(evFork);
    cudaEventDestroy(evJoin);
    cudaStreamDestroy(side);
}

// round 9
// speedup vs baseline: 1.5930x; 1.2546x over previous
#include <cuda_runtime.h>
#include <cuda_bf16.h>
#include <cstdint>

#define NN 50000   // nodes
#define MM 10000   // hyperedges
#define DD 128     // feature dim

// ---------------- static scratch ----------------
__device__ float g_esum [MM * DD];   // hyperedge sums                 5.1 MB
__device__ float g_eproj[MM * DD];   // (esum/cnt) @ Wveu              5.1 MB
__device__ float g_nsum [NN * DD];   // node sums (output space)      25.6 MB
__device__ float g_xout [NN * DD];   // x @ Wvu                       25.6 MB
__device__ float g_wvu  [DD * DD];   // W_v @ W_u_top
__device__ float g_wveu [DD * DD];   // W_v @ W_e @ W_u_bot
__device__ int   g_ecnt [MM];
__device__ int   g_ncnt [NN];
__device__ int   g_colmin = 0x7fffffff;   // idempotent across replays

// ---------------- init: zero accumulators + colmin (fused) ----------------
__global__ void k_init(const int* __restrict__ col, int E) {
    int i = blockIdx.x * blockDim.x + threadIdx.x;
    int stride = gridDim.x * blockDim.x;
    float4 z = make_float4(0.f, 0.f, 0.f, 0.f);
    for (int j = i; j < NN * DD / 4; j += stride) ((float4*)g_nsum)[j] = z;
    for (int j = i; j < MM * DD / 4; j += stride) ((float4*)g_esum)[j] = z;
    for (int j = i; j < NN; j += stride) g_ncnt[j] = 0;
    for (int j = i; j < MM; j += stride) g_ecnt[j] = 0;
    int v = 0x7fffffff;
    for (int j = i; j < E; j += stride) v = min(v, __ldg(&col[j]));
#pragma unroll
    for (int o = 16; o > 0; o >>= 1) v = min(v, __shfl_down_sync(0xffffffffu, v, o));
    if ((threadIdx.x & 31) == 0) atomicMin(&g_colmin, v);
}

// ---------------- weight combos: Wvu = Wv@Wu_top ; Wveu = Wv@We@Wu_bot ----------------
__global__ void __launch_bounds__(128) k_combo(
    const float* __restrict__ Wv, const float* __restrict__ We,
    const float* __restrict__ Wu)
{
    __shared__ float rowv[DD];
    __shared__ float tmp[DD];
    const int c = threadIdx.x;
    const int b = blockIdx.x;
    const float* Wu_top = Wu;
    const float* Wu_bot = Wu + DD * DD;

    if (b < DD) {
        const int r = b;
        rowv[c] = Wv[r * DD + c];
        __syncthreads();
        float a0 = 0.f, a1 = 0.f;
#pragma unroll
        for (int k = 0; k < DD; k += 2) {
            a0 = fmaf(rowv[k],     Wu_top[(k)     * DD + c], a0);
            a1 = fmaf(rowv[k + 1], Wu_top[(k + 1) * DD + c], a1);
        }
        g_wvu[r * DD + c] = a0 + a1;
    } else {
        const int r = b - DD;
        rowv[c] = Wv[r * DD + c];
        __syncthreads();
        float a0 = 0.f, a1 = 0.f;
#pragma unroll
        for (int k = 0; k < DD; k += 2) {
            a0 = fmaf(rowv[k],     We[(k)     * DD + c], a0);
            a1 = fmaf(rowv[k + 1], We[(k + 1) * DD + c], a1);
        }
        tmp[c] = a0 + a1;
        __syncthreads();
        float b0 = 0.f, b1 = 0.f;
#pragma unroll
        for (int k = 0; k < DD; k += 2) {
            b0 = fmaf(tmp[k],     Wu_bot[(k)     * DD + c], b0);
            b1 = fmaf(tmp[k + 1], Wu_bot[(k + 1) * DD + c], b1);
        }
        g_wveu[r * DD + c] = b0 + b1;
    }
}

// ---------------- vector float atomic add (sm_90+) ----------------
__device__ __forceinline__ void red_add_v4(float* p, float4 v) {
    asm volatile("red.global.add.v4.f32 [%0], {%1,%2,%3,%4};"
                 :: "l"(p), "f"(v.x), "f"(v.y), "f"(v.z), "f"(v.w) : "memory");
}

// ---------------- scatter 1: raw node features -> hyperedge sums ----------------
__global__ void k_scatter1(const float* __restrict__ x,
                           const int* __restrict__ row, const int* __restrict__ col, int E) {
    const int cmin = g_colmin;
    const int lane = threadIdx.x & 31;
    const int warp = (blockIdx.x * blockDim.x + threadIdx.x) >> 5;
    const int nw   = (gridDim.x * blockDim.x) >> 5;
    for (int e = warp; e < E; e += nw) {
        int r = __ldg(&row[e]);
        int c = __ldg(&col[e]) - cmin;
        float4 v = *(const float4*)&x[(size_t)r * DD + lane * 4];
        red_add_v4(&g_esum[(size_t)c * DD + lane * 4], v);
        if (lane == 0) atomicAdd(&g_ecnt[c], 1);
    }
}

// ---------------- scatter 2: hyperedge features (output space) -> node sums ----------------
__global__ void k_scatter2(const int* __restrict__ row, const int* __restrict__ col, int E) {
    const int cmin = g_colmin;
    const int lane = threadIdx.x & 31;
    const int warp = (blockIdx.x * blockDim.x + threadIdx.x) >> 5;
    const int nw   = (gridDim.x * blockDim.x) >> 5;
    for (int e = warp; e < E; e += nw) {
        int r = __ldg(&row[e]);
        int c = __ldg(&col[e]) - cmin;
        float4 v = *(const float4*)&g_eproj[(size_t)c * DD + lane * 4];
        red_add_v4(&g_nsum[(size_t)r * DD + lane * 4], v);
        if (lane == 0) atomicAdd(&g_ncnt[r], 1);
    }
}

// ---------------- packed f32x2 FMA helpers ----------------
__device__ __forceinline__ unsigned long long pack_dup(float a) {
    unsigned long long r;
    uint32_t u = __float_as_uint(a);
    asm("mov.b64 %0, {%1, %1};" : "=l"(r) : "r"(u));
    return r;
}
__device__ __forceinline__ void fma_x2(unsigned long long& acc,
                                       unsigned long long a, unsigned long long b) {
    asm("fma.rn.f32x2 %0, %1, %2, %0;" : "+l"(acc) : "l"(a), "l"(b));
}
__device__ __forceinline__ float2 unpack_x2(unsigned long long v) {
    float2 r;
    uint32_t lo, hi;
    asm("mov.b64 {%0, %1}, %2;" : "=r"(lo), "=r"(hi) : "l"(v));
    r.x = __uint_as_float(lo);
    r.y = __uint_as_float(hi);
    return r;
}

// ---------------- double-buffered SGEMM body (f32x2 inner loop) ----------------
// C = A[Mrows x 128] @ B[128 x 128]
// SCALE: A rows scaled by 1/max(cnt[row],1)
template <bool SCALE>
__device__ __forceinline__ void gemm_body(
    const float* __restrict__ A0, const int* __restrict__ cnt0,
    const float* __restrict__ Bm, float* __restrict__ C, int Mrows)
{
    __shared__ float As[2][16][132];
    __shared__ __align__(16) float Bs[2][16][128];

    const int tid = threadIdx.x;
    const int ty = tid >> 4;
    const int tx = tid & 15;
    const int rowBase = blockIdx.x * 128;

    const int aRow = tid >> 2;
    const int aCol = (tid & 3) << 2;
    const int bRow = tid >> 5;
    const int bCol = (tid & 31) << 2;

    float scl[2] = {1.0f, 1.0f};
    if (SCALE) {
#pragma unroll
        for (int p = 0; p < 2; p++) {
            int gr = rowBase + aRow + p * 64;
            if (gr < Mrows) scl[p] = 1.0f / fmaxf((float)__ldg(&cnt0[gr]), 1.0f);
        }
    }

    // packed accumulators: acc2[i][j] holds columns (tx*8+2j, tx*8+2j+1) for row ty*8+i
    unsigned long long acc2[8][4];
#pragma unroll
    for (int i = 0; i < 8; i++)
#pragma unroll
        for (int j = 0; j < 4; j++) acc2[i][j] = 0ull;

    float4 pa[2], pb[2];
#pragma unroll
    for (int p = 0; p < 2; p++) {
        int gr = rowBase + aRow + p * 64;
        pa[p] = make_float4(0.f, 0.f, 0.f, 0.f);
        if (gr < Mrows) {
            pa[p] = *(const float4*)&A0[(size_t)gr * DD + aCol];
            if (SCALE) { pa[p].x *= scl[p]; pa[p].y *= scl[p]; pa[p].z *= scl[p]; pa[p].w *= scl[p]; }
        }
        pb[p] = *(const float4*)&Bm[(size_t)(bRow + p * 8) * DD + bCol];
    }
#pragma unroll
    for (int p = 0; p < 2; p++) {
        int r = aRow + p * 64;
        As[0][aCol + 0][r] = pa[p].x;
        As[0][aCol + 1][r] = pa[p].y;
        As[0][aCol + 2][r] = pa[p].z;
        As[0][aCol + 3][r] = pa[p].w;
        *(float4*)&Bs[0][bRow + p * 8][bCol] = pb[p];
    }
    __syncthreads();

#pragma unroll
    for (int kb = 0; kb < 8; kb++) {
        if (kb < 7) {
            const int ko = (kb + 1) * 16;
#pragma unroll
            for (int p = 0; p < 2; p++) {
                int gr = rowBase + aRow + p * 64;
                pa[p] = make_float4(0.f, 0.f, 0.f, 0.f);
                if (gr < Mrows) {
                    pa[p] = *(const float4*)&A0[(size_t)gr * DD + ko + aCol];
                    if (SCALE) { pa[p].x *= scl[p]; pa[p].y *= scl[p]; pa[p].z *= scl[p]; pa[p].w *= scl[p]; }
                }
                pb[p] = *(const float4*)&Bm[(size_t)(ko + bRow + p * 8) * DD + bCol];
            }
        }
        const int cb = kb & 1;
#pragma unroll
        for (int k = 0; k < 16; k++) {
            float ar[8];
            *(float4*)&ar[0] = *(const float4*)&As[cb][k][ty * 8];
            *(float4*)&ar[4] = *(const float4*)&As[cb][k][ty * 8 + 4];
            // adjacent float pairs in smem are exactly f32x2-packed (little endian)
            const unsigned long long* bp =
                (const unsigned long long*)&Bs[cb][k][tx * 8];
            unsigned long long br2[4];
            br2[0] = bp[0]; br2[1] = bp[1]; br2[2] = bp[2]; br2[3] = bp[3];
#pragma unroll
            for (int i = 0; i < 8; i++) {
                unsigned long long ai = pack_dup(ar[i]);
#pragma unroll
                for (int j = 0; j < 4; j++) fma_x2(acc2[i][j], ai, br2[j]);
            }
        }
        if (kb < 7) {
            const int nb = cb ^ 1;
#pragma unroll
            for (int p = 0; p < 2; p++) {
                int r = aRow + p * 64;
                As[nb][aCol + 0][r] = pa[p].x;
                As[nb][aCol + 1][r] = pa[p].y;
                As[nb][aCol + 2][r] = pa[p].z;
                As[nb][aCol + 3][r] = pa[p].w;
                *(float4*)&Bs[nb][bRow + p * 8][bCol] = pb[p];
            }
            __syncthreads();
        }
    }

#pragma unroll
    for (int i = 0; i < 8; i++) {
        int gr = rowBase + ty * 8 + i;
        if (gr >= Mrows) continue;
#pragma unroll
        for (int j = 0; j < 4; j += 2) {
            float2 v0 = unpack_x2(acc2[i][j]);
            float2 v1 = unpack_x2(acc2[i][j + 1]);
            float4 v = make_float4(v0.x, v0.y, v1.x, v1.y);
            *(float4*)&C[(size_t)gr * DD + tx * 8 + j * 2] = v;
        }
    }
}

__global__ void __launch_bounds__(256, 2) k_gemm_plain(
    const float* A, const float* B, float* C, int Mrows)
{
    gemm_body<false>(A, nullptr, B, C, Mrows);
}

__global__ void __launch_bounds__(256, 2) k_gemm_scale(
    const float* A, const int* cnt, const float* B, float* C, int Mrows)
{
    gemm_body<true>(A, cnt, B, C, Mrows);
}

// ---------------- final fused epilogue: out = relu(xout + nsum/cnt + b) ----------------
__global__ void k_final(const float* __restrict__ bias, float* __restrict__ out, int N) {
    int total = N * (DD / 4);
    for (int i = blockIdx.x * blockDim.x + threadIdx.x; i < total;
         i += gridDim.x * blockDim.x) {
        int r  = i >> 5;
        int cg = i & 31;
        float4 a = *(const float4*)&g_xout[(size_t)i * 4];
        float4 s = *(const float4*)&g_nsum[(size_t)i * 4];
        float inv = 1.0f / fmaxf((float)__ldg(&g_ncnt[r]), 1.0f);
        float4 b = *(const float4*)&bias[cg * 4];
        float4 o;
        o.x = fmaxf(fmaf(s.x, inv, a.x) + b.x, 0.0f);
        o.y = fmaxf(fmaf(s.y, inv, a.y) + b.y, 0.0f);
        o.z = fmaxf(fmaf(s.z, inv, a.z) + b.z, 0.0f);
        o.w = fmaxf(fmaf(s.w, inv, a.w) + b.w, 0.0f);
        *(float4*)&out[(size_t)i * 4] = o;
    }
}

// ---------------- launch ----------------
extern "C" void kernel_launch(void* const* d_in, const int* in_sizes, int n_in,
                              void* d_out, int out_size)
{
    const float* x   = (const float*)d_in[0];
    const int*   ei  = (const int*)  d_in[1];
    const float* Wv  = (const float*)d_in[2];
    const float* We  = (const float*)d_in[3];
    const float* Wu  = (const float*)d_in[4];
    const float* bu  = (const float*)d_in[5];
    float* out = (float*)d_out;

    const int E = in_sizes[1] / 2;
    const int N = in_sizes[0] / DD;
    const int* rowp = ei;
    const int* colp = ei + E;

    float* esum;  cudaGetSymbolAddress((void**)&esum,  g_esum);
    float* eproj; cudaGetSymbolAddress((void**)&eproj, g_eproj);
    float* xout;  cudaGetSymbolAddress((void**)&xout,  g_xout);
    float* wvu;   cudaGetSymbolAddress((void**)&wvu,   g_wvu);
    float* wveu;  cudaGetSymbolAddress((void**)&wveu,  g_wveu);
    int* ecnt;    cudaGetSymbolAddress((void**)&ecnt,  g_ecnt);

    cudaStream_t side;
    cudaStreamCreateWithFlags(&side, cudaStreamNonBlocking);
    cudaEvent_t evFork, evJoin;
    cudaEventCreateWithFlags(&evFork, cudaEventDisableTiming);
    cudaEventCreateWithFlags(&evJoin, cudaEventDisableTiming);

    // main stream: init (zero + colmin), weight combos
    k_init<<<512, 256>>>(colp, E);
    k_combo<<<256, 128>>>(Wv, We, Wu);

    // fork: xout = x @ Wvu on side stream
    cudaEventRecord(evFork, 0);
    cudaStreamWaitEvent(side, evFork, 0);
    k_gemm_plain<<<(N + 127) / 128, 256, 0, side>>>(x, wvu, xout, N);
    cudaEventRecord(evJoin, side);

    // main stream: scatter1 -> gemm_scale -> scatter2
    k_scatter1<<<4096, 256>>>(x, rowp, colp, E);
    k_gemm_scale<<<(MM + 127) / 128, 256>>>(esum, ecnt, wveu, eproj, MM);
    k_scatter2<<<4096, 256>>>(rowp, colp, E);

    // join, then fused epilogue
    cudaStreamWaitEvent(0, evJoin, 0);
    k_final<<<2048, 256>>>(bu, out, N);

    cudaEventDestroy(evFork);
    cudaEventDestroy(evJoin);
    cudaStreamDestroy(side);
}

// round 10
// speedup vs baseline: 1.6649x; 1.0452x over previous
#include <cuda_runtime.h>
#include <cuda_bf16.h>
#include <cstdint>

#define NN 50000   // nodes
#define MM 10000   // hyperedges
#define DD 128     // feature dim

// ---------------- static scratch ----------------
__device__ float g_esum [MM * DD];   // hyperedge sums      5.1 MB
__device__ float g_eproj[MM * DD];   // emean @ Wveu        5.1 MB
__device__ float g_wvu  [DD * DD];   // W_v @ W_u_top
__device__ float g_wveu [DD * DD];   // W_v @ W_e @ W_u_bot
__device__ float g_ninv [NN];        // 1/max(ncnt,1)
__device__ int   g_ecnt [MM];
__device__ int   g_ncnt [NN];
__device__ int   g_colmin = 0x7fffffff;   // idempotent across replays

// ---------------- init: zero esum + counts, colmin ----------------
__global__ void k_init(const int* __restrict__ col, int E) {
    int i = blockIdx.x * blockDim.x + threadIdx.x;
    int stride = gridDim.x * blockDim.x;
    float4 z = make_float4(0.f, 0.f, 0.f, 0.f);
    for (int j = i; j < MM * DD / 4; j += stride) ((float4*)g_esum)[j] = z;
    for (int j = i; j < NN; j += stride) g_ncnt[j] = 0;
    for (int j = i; j < MM; j += stride) g_ecnt[j] = 0;
    int v = 0x7fffffff;
    for (int j = i; j < E; j += stride) v = min(v, __ldg(&col[j]));
#pragma unroll
    for (int o = 16; o > 0; o >>= 1) v = min(v, __shfl_down_sync(0xffffffffu, v, o));
    if ((threadIdx.x & 31) == 0) atomicMin(&g_colmin, v);
}

// ---------------- degree histograms (both directions) ----------------
__global__ void k_hist(const int* __restrict__ row, const int* __restrict__ col, int E) {
    const int cmin = g_colmin;
    for (int e = blockIdx.x * blockDim.x + threadIdx.x; e < E;
         e += gridDim.x * blockDim.x) {
        atomicAdd(&g_ecnt[__ldg(&col[e]) - cmin], 1);
        atomicAdd(&g_ncnt[__ldg(&row[e])], 1);
    }
}

// ---------------- per-node inverse counts ----------------
__global__ void k_ninv() {
    int i = blockIdx.x * blockDim.x + threadIdx.x;
    if (i < NN) g_ninv[i] = 1.0f / fmaxf((float)g_ncnt[i], 1.0f);
}

// ---------------- weight combos: Wvu = Wv@Wu_top ; Wveu = Wv@We@Wu_bot ----------------
__global__ void __launch_bounds__(128) k_combo(
    const float* __restrict__ Wv, const float* __restrict__ We,
    const float* __restrict__ Wu)
{
    __shared__ float rowv[DD];
    __shared__ float tmp[DD];
    const int c = threadIdx.x;
    const int b = blockIdx.x;
    const float* Wu_top = Wu;
    const float* Wu_bot = Wu + DD * DD;

    if (b < DD) {
        const int r = b;
        rowv[c] = Wv[r * DD + c];
        __syncthreads();
        float a0 = 0.f, a1 = 0.f;
#pragma unroll
        for (int k = 0; k < DD; k += 2) {
            a0 = fmaf(rowv[k],     Wu_top[(k)     * DD + c], a0);
            a1 = fmaf(rowv[k + 1], Wu_top[(k + 1) * DD + c], a1);
        }
        g_wvu[r * DD + c] = a0 + a1;
    } else {
        const int r = b - DD;
        rowv[c] = Wv[r * DD + c];
        __syncthreads();
        float a0 = 0.f, a1 = 0.f;
#pragma unroll
        for (int k = 0; k < DD; k += 2) {
            a0 = fmaf(rowv[k],     We[(k)     * DD + c], a0);
            a1 = fmaf(rowv[k + 1], We[(k + 1) * DD + c], a1);
        }
        tmp[c] = a0 + a1;
        __syncthreads();
        float b0 = 0.f, b1 = 0.f;
#pragma unroll
        for (int k = 0; k < DD; k += 2) {
            b0 = fmaf(tmp[k],     Wu_bot[(k)     * DD + c], b0);
            b1 = fmaf(tmp[k + 1], Wu_bot[(k + 1) * DD + c], b1);
        }
        g_wveu[r * DD + c] = b0 + b1;
    }
}

// ---------------- vector float atomic add / L2-only load ----------------
__device__ __forceinline__ void red_add_v4(float* p, float4 v) {
    asm volatile("red.global.add.v4.f32 [%0], {%1,%2,%3,%4};"
                 :: "l"(p), "f"(v.x), "f"(v.y), "f"(v.z), "f"(v.w) : "memory");
}
__device__ __forceinline__ float4 ldcg_v4(const float* p) {
    float4 v;
    asm volatile("ld.global.cg.v4.f32 {%0,%1,%2,%3}, [%4];"
                 : "=f"(v.x), "=f"(v.y), "=f"(v.z), "=f"(v.w) : "l"(p));
    return v;
}

// ---------------- scatter 1: raw node features -> hyperedge sums ----------------
__global__ void k_scatter1(const float* __restrict__ x,
                           const int* __restrict__ row, const int* __restrict__ col, int E) {
    const int cmin = g_colmin;
    const int lane = threadIdx.x & 31;
    const int warp = (blockIdx.x * blockDim.x + threadIdx.x) >> 5;
    const int nw   = (gridDim.x * blockDim.x) >> 5;
    for (int e = warp; e < E; e += 2 * nw) {
        int e2 = e + nw;
        int r0 = __ldg(&row[e]);
        int c0 = __ldg(&col[e]) - cmin;
        float4 v0 = ldcg_v4(&x[(size_t)r0 * DD + lane * 4]);
        if (e2 < E) {
            int r1 = __ldg(&row[e2]);
            int c1 = __ldg(&col[e2]) - cmin;
            float4 v1 = ldcg_v4(&x[(size_t)r1 * DD + lane * 4]);
            red_add_v4(&g_esum[(size_t)c0 * DD + lane * 4], v0);
            red_add_v4(&g_esum[(size_t)c1 * DD + lane * 4], v1);
        } else {
            red_add_v4(&g_esum[(size_t)c0 * DD + lane * 4], v0);
        }
    }
}

// ---------------- scatter 2: pre-scaled eproj rows -> out (bias already there) ----------------
__global__ void k_scatter2(const int* __restrict__ row, const int* __restrict__ col,
                           float* __restrict__ out, int E) {
    const int cmin = g_colmin;
    const int lane = threadIdx.x & 31;
    const int warp = (blockIdx.x * blockDim.x + threadIdx.x) >> 5;
    const int nw   = (gridDim.x * blockDim.x) >> 5;
    for (int e = warp; e < E; e += 2 * nw) {
        int e2 = e + nw;
        int r0 = __ldg(&row[e]);
        int c0 = __ldg(&col[e]) - cmin;
        float s0 = __ldg(&g_ninv[r0]);
        float4 v0 = ldcg_v4(&g_eproj[(size_t)c0 * DD + lane * 4]);
        v0.x *= s0; v0.y *= s0; v0.z *= s0; v0.w *= s0;
        if (e2 < E) {
            int r1 = __ldg(&row[e2]);
            int c1 = __ldg(&col[e2]) - cmin;
            float s1 = __ldg(&g_ninv[r1]);
            float4 v1 = ldcg_v4(&g_eproj[(size_t)c1 * DD + lane * 4]);
            v1.x *= s1; v1.y *= s1; v1.z *= s1; v1.w *= s1;
            red_add_v4(&out[(size_t)r0 * DD + lane * 4], v0);
            red_add_v4(&out[(size_t)r1 * DD + lane * 4], v1);
        } else {
            red_add_v4(&out[(size_t)r0 * DD + lane * 4], v0);
        }
    }
}

// ---------------- packed f32x2 FMA helpers ----------------
__device__ __forceinline__ unsigned long long pack_dup(float a) {
    unsigned long long r;
    uint32_t u = __float_as_uint(a);
    asm("mov.b64 %0, {%1, %1};" : "=l"(r) : "r"(u));
    return r;
}
__device__ __forceinline__ void fma_x2(unsigned long long& acc,
                                       unsigned long long a, unsigned long long b) {
    asm("fma.rn.f32x2 %0, %1, %2, %0;" : "+l"(acc) : "l"(a), "l"(b));
}
__device__ __forceinline__ float2 unpack_x2(unsigned long long v) {
    float2 r;
    uint32_t lo, hi;
    asm("mov.b64 {%0, %1}, %2;" : "=r"(lo), "=r"(hi) : "l"(v));
    r.x = __uint_as_float(lo);
    r.y = __uint_as_float(hi);
    return r;
}

// ---------------- double-buffered SGEMM body (f32x2 inner loop) ----------------
// SCALE: A rows scaled by 1/max(cnt[row],1) ; BIAS: C = acc + bias (no relu)
template <bool SCALE, bool BIAS>
__device__ __forceinline__ void gemm_body(
    const float* __restrict__ A0, const int* __restrict__ cnt0,
    const float* __restrict__ Bm, const float* __restrict__ bias,
    float* __restrict__ C, int Mrows)
{
    __shared__ float As[2][16][132];
    __shared__ __align__(16) float Bs[2][16][128];

    const int tid = threadIdx.x;
    const int ty = tid >> 4;
    const int tx = tid & 15;
    const int rowBase = blockIdx.x * 128;

    const int aRow = tid >> 2;
    const int aCol = (tid & 3) << 2;
    const int bRow = tid >> 5;
    const int bCol = (tid & 31) << 2;

    float scl[2] = {1.0f, 1.0f};
    if (SCALE) {
#pragma unroll
        for (int p = 0; p < 2; p++) {
            int gr = rowBase + aRow + p * 64;
            if (gr < Mrows) scl[p] = 1.0f / fmaxf((float)__ldg(&cnt0[gr]), 1.0f);
        }
    }

    unsigned long long acc2[8][4];
#pragma unroll
    for (int i = 0; i < 8; i++)
#pragma unroll
        for (int j = 0; j < 4; j++) acc2[i][j] = 0ull;

    float4 pa[2], pb[2];
#pragma unroll
    for (int p = 0; p < 2; p++) {
        int gr = rowBase + aRow + p * 64;
        pa[p] = make_float4(0.f, 0.f, 0.f, 0.f);
        if (gr < Mrows) {
            pa[p] = *(const float4*)&A0[(size_t)gr * DD + aCol];
            if (SCALE) { pa[p].x *= scl[p]; pa[p].y *= scl[p]; pa[p].z *= scl[p]; pa[p].w *= scl[p]; }
        }
        pb[p] = *(const float4*)&Bm[(size_t)(bRow + p * 8) * DD + bCol];
    }
#pragma unroll
    for (int p = 0; p < 2; p++) {
        int r = aRow + p * 64;
        As[0][aCol + 0][r] = pa[p].x;
        As[0][aCol + 1][r] = pa[p].y;
        As[0][aCol + 2][r] = pa[p].z;
        As[0][aCol + 3][r] = pa[p].w;
        *(float4*)&Bs[0][bRow + p * 8][bCol] = pb[p];
    }
    __syncthreads();

#pragma unroll
    for (int kb = 0; kb < 8; kb++) {
        if (kb < 7) {
            const int ko = (kb + 1) * 16;
#pragma unroll
            for (int p = 0; p < 2; p++) {
                int gr = rowBase + aRow + p * 64;
                pa[p] = make_float4(0.f, 0.f, 0.f, 0.f);
                if (gr < Mrows) {
                    pa[p] = *(const float4*)&A0[(size_t)gr * DD + ko + aCol];
                    if (SCALE) { pa[p].x *= scl[p]; pa[p].y *= scl[p]; pa[p].z *= scl[p]; pa[p].w *= scl[p]; }
                }
                pb[p] = *(const float4*)&Bm[(size_t)(ko + bRow + p * 8) * DD + bCol];
            }
        }
        const int cb = kb & 1;
#pragma unroll
        for (int k = 0; k < 16; k++) {
            float ar[8];
            *(float4*)&ar[0] = *(const float4*)&As[cb][k][ty * 8];
            *(float4*)&ar[4] = *(const float4*)&As[cb][k][ty * 8 + 4];
            const unsigned long long* bp =
                (const unsigned long long*)&Bs[cb][k][tx * 8];
            unsigned long long br2[4];
            br2[0] = bp[0]; br2[1] = bp[1]; br2[2] = bp[2]; br2[3] = bp[3];
#pragma unroll
            for (int i = 0; i < 8; i++) {
                unsigned long long ai = pack_dup(ar[i]);
#pragma unroll
                for (int j = 0; j < 4; j++) fma_x2(acc2[i][j], ai, br2[j]);
            }
        }
        if (kb < 7) {
            const int nb = cb ^ 1;
#pragma unroll
            for (int p = 0; p < 2; p++) {
                int r = aRow + p * 64;
                As[nb][aCol + 0][r] = pa[p].x;
                As[nb][aCol + 1][r] = pa[p].y;
                As[nb][aCol + 2][r] = pa[p].z;
                As[nb][aCol + 3][r] = pa[p].w;
                *(float4*)&Bs[nb][bRow + p * 8][bCol] = pb[p];
            }
            __syncthreads();
        }
    }

#pragma unroll
    for (int i = 0; i < 8; i++) {
        int gr = rowBase + ty * 8 + i;
        if (gr >= Mrows) continue;
#pragma unroll
        for (int j = 0; j < 4; j += 2) {
            float2 v0 = unpack_x2(acc2[i][j]);
            float2 v1 = unpack_x2(acc2[i][j + 1]);
            float4 v = make_float4(v0.x, v0.y, v1.x, v1.y);
            int gc = tx * 8 + j * 2;
            if (BIAS) {
                v.x += __ldg(&bias[gc + 0]);
                v.y += __ldg(&bias[gc + 1]);
                v.z += __ldg(&bias[gc + 2]);
                v.w += __ldg(&bias[gc + 3]);
            }
            *(float4*)&C[(size_t)gr * DD + gc] = v;
        }
    }
}

__global__ void __launch_bounds__(256, 2) k_gemm_bias(
    const float* A, const float* B, const float* bias, float* C, int Mrows)
{
    gemm_body<false, true>(A, nullptr, B, bias, C, Mrows);
}

__global__ void __launch_bounds__(256, 2) k_gemm_scale(
    const float* A, const int* cnt, const float* B, float* C, int Mrows)
{
    gemm_body<true, false>(A, cnt, B, nullptr, C, Mrows);
}

// ---------------- in-place relu ----------------
__global__ void k_relu(float* __restrict__ out, int N) {
    int total = N * (DD / 4);
    for (int i = blockIdx.x * blockDim.x + threadIdx.x; i < total;
         i += gridDim.x * blockDim.x) {
        float4 v = *(const float4*)&out[(size_t)i * 4];
        v.x = fmaxf(v.x, 0.0f);
        v.y = fmaxf(v.y, 0.0f);
        v.z = fmaxf(v.z, 0.0f);
        v.w = fmaxf(v.w, 0.0f);
        *(float4*)&out[(size_t)i * 4] = v;
    }
}

// ---------------- launch ----------------
extern "C" void kernel_launch(void* const* d_in, const int* in_sizes, int n_in,
                              void* d_out, int out_size)
{
    const float* x   = (const float*)d_in[0];
    const int*   ei  = (const int*)  d_in[1];
    const float* Wv  = (const float*)d_in[2];
    const float* We  = (const float*)d_in[3];
    const float* Wu  = (const float*)d_in[4];
    const float* bu  = (const float*)d_in[5];
    float* out = (float*)d_out;

    const int E = in_sizes[1] / 2;
    const int N = in_sizes[0] / DD;
    const int* rowp = ei;
    const int* colp = ei + E;

    float* esum;  cudaGetSymbolAddress((void**)&esum,  g_esum);
    float* eproj; cudaGetSymbolAddress((void**)&eproj, g_eproj);
    float* wvu;   cudaGetSymbolAddress((void**)&wvu,   g_wvu);
    float* wveu;  cudaGetSymbolAddress((void**)&wveu,  g_wveu);
    int* ecnt;    cudaGetSymbolAddress((void**)&ecnt,  g_ecnt);

    cudaStream_t side;
    cudaStreamCreateWithFlags(&side, cudaStreamNonBlocking);
    cudaEvent_t evFork, evJoin;
    cudaEventCreateWithFlags(&evFork, cudaEventDisableTiming);
    cudaEventCreateWithFlags(&evJoin, cudaEventDisableTiming);

    // fork side stream at entry: combo -> out = x@Wvu + bias
    cudaEventRecord(evFork, 0);
    cudaStreamWaitEvent(side, evFork, 0);
    k_combo<<<256, 128, 0, side>>>(Wv, We, Wu);
    k_gemm_bias<<<(N + 127) / 128, 256, 0, side>>>(x, wvu, bu, out, N);
    cudaEventRecord(evJoin, side);

    // main: init -> hist -> ninv -> scatter1 -> gemm_scale
    k_init<<<512, 256>>>(colp, E);
    k_hist<<<512, 256>>>(rowp, colp, E);
    k_ninv<<<(NN + 255) / 256, 256>>>();
    k_scatter1<<<4096, 256>>>(x, rowp, colp, E);
    k_gemm_scale<<<(MM + 127) / 128, 256>>>(esum, ecnt, wveu, eproj, MM);

    // join side GEMM, then scatter pre-scaled contributions into out, relu in place
    cudaStreamWaitEvent(0, evJoin, 0);
    k_scatter2<<<4096, 256>>>(rowp, colp, out, E);
    k_relu<<<2048, 256>>>(out, N);

    cudaEventDestroy(evFork);
    cudaEventDestroy(evJoin);
    cudaStreamDestroy(side);
}

// round 11
// speedup vs baseline: 1.6984x; 1.0201x over previous
#include <cuda_runtime.h>
#include <cuda_bf16.h>
#include <cstdint>

#define NN 50000   // nodes
#define MM 10000   // hyperedges
#define DD 128     // feature dim

// ---------------- static scratch ----------------
__device__ float g_esum [MM * DD];   // hyperedge sums      5.1 MB
__device__ float g_eproj[MM * DD];   // emean @ Wveu        5.1 MB
__device__ float g_wvu  [DD * DD];   // W_v @ W_u_top
__device__ float g_wveu [DD * DD];   // W_v @ W_e @ W_u_bot
__device__ float g_ninv [NN];        // 1/max(ncnt,1)
__device__ int   g_ecnt [MM];
__device__ int   g_ncnt [NN];
__device__ int   g_colmin = 0x7fffffff;   // idempotent across replays

// ---------------- init: zero esum + counts, colmin ----------------
__global__ void k_init(const int* __restrict__ col, int E) {
    int i = blockIdx.x * blockDim.x + threadIdx.x;
    int stride = gridDim.x * blockDim.x;
    float4 z = make_float4(0.f, 0.f, 0.f, 0.f);
    for (int j = i; j < MM * DD / 4; j += stride) ((float4*)g_esum)[j] = z;
    for (int j = i; j < NN; j += stride) g_ncnt[j] = 0;
    for (int j = i; j < MM; j += stride) g_ecnt[j] = 0;
    int v = 0x7fffffff;
    for (int j = i; j < E; j += stride) v = min(v, __ldg(&col[j]));
#pragma unroll
    for (int o = 16; o > 0; o >>= 1) v = min(v, __shfl_down_sync(0xffffffffu, v, o));
    if ((threadIdx.x & 31) == 0) atomicMin(&g_colmin, v);
}

// ---------------- degree histograms (both directions, wide + unrolled) ----------------
__global__ void k_hist(const int* __restrict__ row, const int* __restrict__ col, int E) {
    const int cmin = g_colmin;
    const int tid = blockIdx.x * blockDim.x + threadIdx.x;
    const int stride = gridDim.x * blockDim.x;
    for (int e = tid; e < E; e += 2 * stride) {
        int e2 = e + stride;
        int c0 = __ldg(&col[e]) - cmin;
        int r0 = __ldg(&row[e]);
        if (e2 < E) {
            int c1 = __ldg(&col[e2]) - cmin;
            int r1 = __ldg(&row[e2]);
            atomicAdd(&g_ecnt[c0], 1);
            atomicAdd(&g_ecnt[c1], 1);
            atomicAdd(&g_ncnt[r0], 1);
            atomicAdd(&g_ncnt[r1], 1);
        } else {
            atomicAdd(&g_ecnt[c0], 1);
            atomicAdd(&g_ncnt[r0], 1);
        }
    }
}

// ---------------- per-node inverse counts ----------------
__global__ void k_ninv() {
    int i = blockIdx.x * blockDim.x + threadIdx.x;
    if (i < NN) g_ninv[i] = 1.0f / fmaxf((float)g_ncnt[i], 1.0f);
}

// ---------------- weight combos: Wvu = Wv@Wu_top ; Wveu = Wv@We@Wu_bot ----------------
__global__ void __launch_bounds__(128) k_combo(
    const float* __restrict__ Wv, const float* __restrict__ We,
    const float* __restrict__ Wu)
{
    __shared__ float rowv[DD];
    __shared__ float tmp[DD];
    const int c = threadIdx.x;
    const int b = blockIdx.x;
    const float* Wu_top = Wu;
    const float* Wu_bot = Wu + DD * DD;

    if (b < DD) {
        const int r = b;
        rowv[c] = Wv[r * DD + c];
        __syncthreads();
        float a0 = 0.f, a1 = 0.f;
#pragma unroll
        for (int k = 0; k < DD; k += 2) {
            a0 = fmaf(rowv[k],     Wu_top[(k)     * DD + c], a0);
            a1 = fmaf(rowv[k + 1], Wu_top[(k + 1) * DD + c], a1);
        }
        g_wvu[r * DD + c] = a0 + a1;
    } else {
        const int r = b - DD;
        rowv[c] = Wv[r * DD + c];
        __syncthreads();
        float a0 = 0.f, a1 = 0.f;
#pragma unroll
        for (int k = 0; k < DD; k += 2) {
            a0 = fmaf(rowv[k],     We[(k)     * DD + c], a0);
            a1 = fmaf(rowv[k + 1], We[(k + 1) * DD + c], a1);
        }
        tmp[c] = a0 + a1;
        __syncthreads();
        float b0 = 0.f, b1 = 0.f;
#pragma unroll
        for (int k = 0; k < DD; k += 2) {
            b0 = fmaf(tmp[k],     Wu_bot[(k)     * DD + c], b0);
            b1 = fmaf(tmp[k + 1], Wu_bot[(k + 1) * DD + c], b1);
        }
        g_wveu[r * DD + c] = b0 + b1;
    }
}

// ---------------- vector float atomic add / L2-only load ----------------
__device__ __forceinline__ void red_add_v4(float* p, float4 v) {
    asm volatile("red.global.add.v4.f32 [%0], {%1,%2,%3,%4};"
                 :: "l"(p), "f"(v.x), "f"(v.y), "f"(v.z), "f"(v.w) : "memory");
}
__device__ __forceinline__ float4 ldcg_v4(const float* p) {
    float4 v;
    asm volatile("ld.global.cg.v4.f32 {%0,%1,%2,%3}, [%4];"
                 : "=f"(v.x), "=f"(v.y), "=f"(v.z), "=f"(v.w) : "l"(p));
    return v;
}

// ---------------- scatter 1: raw node features -> hyperedge sums ----------------
__global__ void k_scatter1(const float* __restrict__ x,
                           const int* __restrict__ row, const int* __restrict__ col, int E) {
    const int cmin = g_colmin;
    const int lane = threadIdx.x & 31;
    const int warp = (blockIdx.x * blockDim.x + threadIdx.x) >> 5;
    const int nw   = (gridDim.x * blockDim.x) >> 5;
    for (int e = warp; e < E; e += 2 * nw) {
        int e2 = e + nw;
        int r0 = __ldg(&row[e]);
        int c0 = __ldg(&col[e]) - cmin;
        float4 v0 = ldcg_v4(&x[(size_t)r0 * DD + lane * 4]);
        if (e2 < E) {
            int r1 = __ldg(&row[e2]);
            int c1 = __ldg(&col[e2]) - cmin;
            float4 v1 = ldcg_v4(&x[(size_t)r1 * DD + lane * 4]);
            red_add_v4(&g_esum[(size_t)c0 * DD + lane * 4], v0);
            red_add_v4(&g_esum[(size_t)c1 * DD + lane * 4], v1);
        } else {
            red_add_v4(&g_esum[(size_t)c0 * DD + lane * 4], v0);
        }
    }
}

// ---------------- scatter 2: pre-scaled eproj rows -> out (bias already there) ----------------
__global__ void k_scatter2(const int* __restrict__ row, const int* __restrict__ col,
                           float* __restrict__ out, int E) {
    const int cmin = g_colmin;
    const int lane = threadIdx.x & 31;
    const int warp = (blockIdx.x * blockDim.x + threadIdx.x) >> 5;
    const int nw   = (gridDim.x * blockDim.x) >> 5;
    for (int e = warp; e < E; e += 2 * nw) {
        int e2 = e + nw;
        int r0 = __ldg(&row[e]);
        int c0 = __ldg(&col[e]) - cmin;
        float s0 = __ldg(&g_ninv[r0]);
        float4 v0 = ldcg_v4(&g_eproj[(size_t)c0 * DD + lane * 4]);
        v0.x *= s0; v0.y *= s0; v0.z *= s0; v0.w *= s0;
        if (e2 < E) {
            int r1 = __ldg(&row[e2]);
            int c1 = __ldg(&col[e2]) - cmin;
            float s1 = __ldg(&g_ninv[r1]);
            float4 v1 = ldcg_v4(&g_eproj[(size_t)c1 * DD + lane * 4]);
            v1.x *= s1; v1.y *= s1; v1.z *= s1; v1.w *= s1;
            red_add_v4(&out[(size_t)r0 * DD + lane * 4], v0);
            red_add_v4(&out[(size_t)r1 * DD + lane * 4], v1);
        } else {
            red_add_v4(&out[(size_t)r0 * DD + lane * 4], v0);
        }
    }
}

// ---------------- packed f32x2 FMA helpers ----------------
__device__ __forceinline__ unsigned long long pack_dup(float a) {
    unsigned long long r;
    uint32_t u = __float_as_uint(a);
    asm("mov.b64 %0, {%1, %1};" : "=l"(r) : "r"(u));
    return r;
}
__device__ __forceinline__ void fma_x2(unsigned long long& acc,
                                       unsigned long long a, unsigned long long b) {
    asm("fma.rn.f32x2 %0, %1, %2, %0;" : "+l"(acc) : "l"(a), "l"(b));
}
__device__ __forceinline__ float2 unpack_x2(unsigned long long v) {
    float2 r;
    uint32_t lo, hi;
    asm("mov.b64 {%0, %1}, %2;" : "=r"(lo), "=r"(hi) : "l"(v));
    r.x = __uint_as_float(lo);
    r.y = __uint_as_float(hi);
    return r;
}

// ---------------- double-buffered SGEMM body (f32x2 inner loop) ----------------
template <bool SCALE, bool BIAS>
__device__ __forceinline__ void gemm_body(
    const float* __restrict__ A0, const int* __restrict__ cnt0,
    const float* __restrict__ Bm, const float* __restrict__ bias,
    float* __restrict__ C, int Mrows)
{
    __shared__ float As[2][16][132];
    __shared__ __align__(16) float Bs[2][16][128];

    const int tid = threadIdx.x;
    const int ty = tid >> 4;
    const int tx = tid & 15;
    const int rowBase = blockIdx.x * 128;

    const int aRow = tid >> 2;
    const int aCol = (tid & 3) << 2;
    const int bRow = tid >> 5;
    const int bCol = (tid & 31) << 2;

    float scl[2] = {1.0f, 1.0f};
    if (SCALE) {
#pragma unroll
        for (int p = 0; p < 2; p++) {
            int gr = rowBase + aRow + p * 64;
            if (gr < Mrows) scl[p] = 1.0f / fmaxf((float)__ldg(&cnt0[gr]), 1.0f);
        }
    }

    unsigned long long acc2[8][4];
#pragma unroll
    for (int i = 0; i < 8; i++)
#pragma unroll
        for (int j = 0; j < 4; j++) acc2[i][j] = 0ull;

    float4 pa[2], pb[2];
#pragma unroll
    for (int p = 0; p < 2; p++) {
        int gr = rowBase + aRow + p * 64;
        pa[p] = make_float4(0.f, 0.f, 0.f, 0.f);
        if (gr < Mrows) {
            pa[p] = *(const float4*)&A0[(size_t)gr * DD + aCol];
            if (SCALE) { pa[p].x *= scl[p]; pa[p].y *= scl[p]; pa[p].z *= scl[p]; pa[p].w *= scl[p]; }
        }
        pb[p] = *(const float4*)&Bm[(size_t)(bRow + p * 8) * DD + bCol];
    }
#pragma unroll
    for (int p = 0; p < 2; p++) {
        int r = aRow + p * 64;
        As[0][aCol + 0][r] = pa[p].x;
        As[0][aCol + 1][r] = pa[p].y;
        As[0][aCol + 2][r] = pa[p].z;
        As[0][aCol + 3][r] = pa[p].w;
        *(float4*)&Bs[0][bRow + p * 8][bCol] = pb[p];
    }
    __syncthreads();

#pragma unroll
    for (int kb = 0; kb < 8; kb++) {
        if (kb < 7) {
            const int ko = (kb + 1) * 16;
#pragma unroll
            for (int p = 0; p < 2; p++) {
                int gr = rowBase + aRow + p * 64;
                pa[p] = make_float4(0.f, 0.f, 0.f, 0.f);
                if (gr < Mrows) {
                    pa[p] = *(const float4*)&A0[(size_t)gr * DD + ko + aCol];
                    if (SCALE) { pa[p].x *= scl[p]; pa[p].y *= scl[p]; pa[p].z *= scl[p]; pa[p].w *= scl[p]; }
                }
                pb[p] = *(const float4*)&Bm[(size_t)(ko + bRow + p * 8) * DD + bCol];
            }
        }
        const int cb = kb & 1;
#pragma unroll
        for (int k = 0; k < 16; k++) {
            float ar[8];
            *(float4*)&ar[0] = *(const float4*)&As[cb][k][ty * 8];
            *(float4*)&ar[4] = *(const float4*)&As[cb][k][ty * 8 + 4];
            const unsigned long long* bp =
                (const unsigned long long*)&Bs[cb][k][tx * 8];
            unsigned long long br2[4];
            br2[0] = bp[0]; br2[1] = bp[1]; br2[2] = bp[2]; br2[3] = bp[3];
#pragma unroll
            for (int i = 0; i < 8; i++) {
                unsigned long long ai = pack_dup(ar[i]);
#pragma unroll
                for (int j = 0; j < 4; j++) fma_x2(acc2[i][j], ai, br2[j]);
            }
        }
        if (kb < 7) {
            const int nb = cb ^ 1;
#pragma unroll
            for (int p = 0; p < 2; p++) {
                int r = aRow + p * 64;
                As[nb][aCol + 0][r] = pa[p].x;
                As[nb][aCol + 1][r] = pa[p].y;
                As[nb][aCol + 2][r] = pa[p].z;
                As[nb][aCol + 3][r] = pa[p].w;
                *(float4*)&Bs[nb][bRow + p * 8][bCol] = pb[p];
            }
            __syncthreads();
        }
    }

#pragma unroll
    for (int i = 0; i < 8; i++) {
        int gr = rowBase + ty * 8 + i;
        if (gr >= Mrows) continue;
#pragma unroll
        for (int j = 0; j < 4; j += 2) {
            float2 v0 = unpack_x2(acc2[i][j]);
            float2 v1 = unpack_x2(acc2[i][j + 1]);
            float4 v = make_float4(v0.x, v0.y, v1.x, v1.y);
            int gc = tx * 8 + j * 2;
            if (BIAS) {
                v.x += __ldg(&bias[gc + 0]);
                v.y += __ldg(&bias[gc + 1]);
                v.z += __ldg(&bias[gc + 2]);
                v.w += __ldg(&bias[gc + 3]);
            }
            *(float4*)&C[(size_t)gr * DD + gc] = v;
        }
    }
}

__global__ void __launch_bounds__(256, 2) k_gemm_bias(
    const float* A, const float* B, const float* bias, float* C, int Mrows)
{
    gemm_body<false, true>(A, nullptr, B, bias, C, Mrows);
}

__global__ void __launch_bounds__(256, 2) k_gemm_scale(
    const float* A, const int* cnt, const float* B, float* C, int Mrows)
{
    gemm_body<true, false>(A, cnt, B, nullptr, C, Mrows);
}

// ---------------- in-place relu ----------------
__global__ void k_relu(float* __restrict__ out, int N) {
    int total = N * (DD / 4);
    for (int i = blockIdx.x * blockDim.x + threadIdx.x; i < total;
         i += gridDim.x * blockDim.x) {
        float4 v = *(const float4*)&out[(size_t)i * 4];
        v.x = fmaxf(v.x, 0.0f);
        v.y = fmaxf(v.y, 0.0f);
        v.z = fmaxf(v.z, 0.0f);
        v.w = fmaxf(v.w, 0.0f);
        *(float4*)&out[(size_t)i * 4] = v;
    }
}

// ---------------- launch ----------------
extern "C" void kernel_launch(void* const* d_in, const int* in_sizes, int n_in,
                              void* d_out, int out_size)
{
    const float* x   = (const float*)d_in[0];
    const int*   ei  = (const int*)  d_in[1];
    const float* Wv  = (const float*)d_in[2];
    const float* We  = (const float*)d_in[3];
    const float* Wu  = (const float*)d_in[4];
    const float* bu  = (const float*)d_in[5];
    float* out = (float*)d_out;

    const int E = in_sizes[1] / 2;
    const int N = in_sizes[0] / DD;
    const int* rowp = ei;
    const int* colp = ei + E;

    float* esum;  cudaGetSymbolAddress((void**)&esum,  g_esum);
    float* eproj; cudaGetSymbolAddress((void**)&eproj, g_eproj);
    float* wvu;   cudaGetSymbolAddress((void**)&wvu,   g_wvu);
    float* wveu;  cudaGetSymbolAddress((void**)&wveu,  g_wveu);
    int* ecnt;    cudaGetSymbolAddress((void**)&ecnt,  g_ecnt);

    cudaStream_t side1, side2;
    cudaStreamCreateWithFlags(&side1, cudaStreamNonBlocking);
    cudaStreamCreateWithFlags(&side2, cudaStreamNonBlocking);
    cudaEvent_t evEntry, evInit, evGemm, evHist;
    cudaEventCreateWithFlags(&evEntry, cudaEventDisableTiming);
    cudaEventCreateWithFlags(&evInit,  cudaEventDisableTiming);
    cudaEventCreateWithFlags(&evGemm,  cudaEventDisableTiming);
    cudaEventCreateWithFlags(&evHist,  cudaEventDisableTiming);

    // side1 (forks at entry): combo -> out = x@Wvu + bias
    cudaEventRecord(evEntry, 0);
    cudaStreamWaitEvent(side1, evEntry, 0);
    k_combo<<<256, 128, 0, side1>>>(Wv, We, Wu);
    k_gemm_bias<<<(N + 127) / 128, 256, 0, side1>>>(x, wvu, bu, out, N);
    cudaEventRecord(evGemm, side1);

    // main: init (zero + colmin)
    k_init<<<512, 256>>>(colp, E);
    cudaEventRecord(evInit, 0);

    // side2 (forks after init): hist -> ninv, overlapped with scatter1
    cudaStreamWaitEvent(side2, evInit, 0);
    k_hist<<<2048, 256, 0, side2>>>(rowp, colp, E);
    k_ninv<<<(NN + 255) / 256, 256, 0, side2>>>();
    cudaEventRecord(evHist, side2);

    // main: scatter1, then (after hist) gemm_scale
    k_scatter1<<<4096, 256>>>(x, rowp, colp, E);
    cudaStreamWaitEvent(0, evHist, 0);
    k_gemm_scale<<<(MM + 127) / 128, 256>>>(esum, ecnt, wveu, eproj, MM);

    // join side GEMM, scatter pre-scaled contributions into out, relu in place
    cudaStreamWaitEvent(0, evGemm, 0);
    k_scatter2<<<4096, 256>>>(rowp, colp, out, E);
    k_relu<<<2048, 256>>>(out, N);

    cudaEventDestroy(evEntry);
    cudaEventDestroy(evInit);
    cudaEventDestroy(evGemm);
    cudaEventDestroy(evHist);
    cudaStreamDestroy(side1);
    cudaStreamDestroy(side2);
}